// round 1
// baseline (speedup 1.0000x reference)
#include <cuda_runtime.h>
#include <math.h>

// Problem constants
constexpr int BATCH = 4;
constexpr int CH    = 256;
constexpr int SPA   = 4096;       // H*W = 64*64
constexpr int NGRP  = 8;
constexpr int CPG   = CH / NGRP;  // 32 channels per group
constexpr int NH    = 4;
constexpr int HD    = CH / NH;    // 64
constexpr float EPS = 1e-5f;
constexpr float SCALE = 0.125f;   // 64^-0.5

constexpr int GRP_ELEMS = CPG * SPA;   // 131072 elements per (b,g)
constexpr int PARTS = 32;              // partial blocks per group

// Scratch (device globals: no allocation allowed)
__device__ float g_xn  [(size_t)BATCH * CH  * SPA];   // 16 MB  groupnorm output
__device__ float g_qkv [(size_t)BATCH * 3*CH * SPA];  // 48 MB  qkv
__device__ float g_ao  [(size_t)BATCH * CH  * SPA];   // 16 MB  attention output
__device__ float g_part[BATCH * NGRP][PARTS][2];      // partial sums
__device__ float g_mean[BATCH * NGRP];
__device__ float g_rinv[BATCH * NGRP];

// ---------------------------------------------------------------------------
// GroupNorm stage 1: per-(group,part) partial sum / sumsq
// ---------------------------------------------------------------------------
__global__ __launch_bounds__(256) void k_gn_part(const float* __restrict__ x) {
    int part = blockIdx.x & (PARTS - 1);
    int bg   = blockIdx.x / PARTS;
    const float4* base = reinterpret_cast<const float4*>(x + (size_t)bg * GRP_ELEMS)
                         + (size_t)part * (GRP_ELEMS / PARTS / 4);
    const int n4 = GRP_ELEMS / PARTS / 4;   // 1024 float4 per part

    float s = 0.f, s2 = 0.f;
    for (int i = threadIdx.x; i < n4; i += 256) {
        float4 v = base[i];
        s  += v.x + v.y + v.z + v.w;
        s2 += v.x*v.x + v.y*v.y + v.z*v.z + v.w*v.w;
    }
    // block reduce (8 warps)
    __shared__ float sh[16];
    for (int o = 16; o; o >>= 1) {
        s  += __shfl_xor_sync(0xffffffffu, s,  o);
        s2 += __shfl_xor_sync(0xffffffffu, s2, o);
    }
    if ((threadIdx.x & 31) == 0) {
        int w = threadIdx.x >> 5;
        sh[w*2] = s; sh[w*2+1] = s2;
    }
    __syncthreads();
    if (threadIdx.x == 0) {
        float a = 0.f, b = 0.f;
        #pragma unroll
        for (int i = 0; i < 8; i++) { a += sh[i*2]; b += sh[i*2+1]; }
        g_part[bg][part][0] = a;
        g_part[bg][part][1] = b;
    }
}

// ---------------------------------------------------------------------------
// GroupNorm stage 2: finalize mean / rsqrt(var+eps). 32 groups, 1 block.
// ---------------------------------------------------------------------------
__global__ void k_gn_final() {
    int g = threadIdx.x;
    if (g >= BATCH * NGRP) return;
    float s = 0.f, s2 = 0.f;
    #pragma unroll
    for (int p = 0; p < PARTS; p++) { s += g_part[g][p][0]; s2 += g_part[g][p][1]; }
    const float invN = 1.0f / (float)GRP_ELEMS;
    float mean = s * invN;
    float var  = s2 * invN - mean * mean;
    g_mean[g] = mean;
    g_rinv[g] = rsqrtf(var + EPS);
}

// ---------------------------------------------------------------------------
// GroupNorm stage 3: normalize elementwise (vectorized)
// ---------------------------------------------------------------------------
__global__ __launch_bounds__(256) void k_gn_norm(const float* __restrict__ x,
                                                 const float* __restrict__ gamma,
                                                 const float* __restrict__ beta) {
    int idx4 = blockIdx.x * 256 + threadIdx.x;
    if (idx4 >= (BATCH * CH * SPA) / 4) return;
    int idx = idx4 * 4;
    int c  = (idx >> 12) & (CH - 1);   // SPA = 4096 = 2^12
    int bg = idx >> 17;                // GRP_ELEMS = 2^17
    float mean = g_mean[bg], rinv = g_rinv[bg];
    float ga = gamma[c] * rinv;
    float be = beta[c] - mean * ga;
    float4 v = reinterpret_cast<const float4*>(x)[idx4];
    float4 o;
    o.x = v.x * ga + be; o.y = v.y * ga + be;
    o.z = v.z * ga + be; o.w = v.w * ga + be;
    reinterpret_cast<float4*>(g_xn)[idx4] = o;
}

// ---------------------------------------------------------------------------
// Tiled SGEMM: Y[b][o][s] = sum_c W[o][c] * X[b][c][s] + bias[o] (+ resid)
// Tile 64x64, K-step 16, 16x16 threads, 4x4 per thread.
// ---------------------------------------------------------------------------
template<bool RESID>
__global__ __launch_bounds__(256) void k_gemm(const float* __restrict__ Wm,
                                              const float* __restrict__ bias,
                                              const float* __restrict__ X,
                                              float* __restrict__ Y,
                                              const float* __restrict__ resid,
                                              int M) {
    __shared__ float As[16][68];   // As[k][m]   (W tile, transposed)
    __shared__ float Bs[16][64];   // Bs[k][n]   (X tile)

    const int b  = blockIdx.z;
    const int o0 = blockIdx.y * 64;
    const int s0 = blockIdx.x * 64;
    const int tx = threadIdx.x, ty = threadIdx.y;
    const int tid = ty * 16 + tx;
    const float* Xb = X + (size_t)b * CH * SPA;

    float acc[4][4] = {};

    for (int k0 = 0; k0 < CH; k0 += 16) {
        // load W tile: W[o0+op][k0+cp] -> As[cp][op]
        {
            int cp = tid & 15;
            int ob = (tid >> 4) * 4;
            #pragma unroll
            for (int r = 0; r < 4; r++)
                As[cp][ob + r] = Wm[(size_t)(o0 + ob + r) * CH + k0 + cp];
        }
        // load X tile: X[k0+kk][s0+ss] -> Bs[kk][ss]
        {
            int ss = tid & 63;
            int kb = tid >> 6;   // 0..3
            #pragma unroll
            for (int r = 0; r < 4; r++) {
                int kk = kb * 4 + r;
                Bs[kk][ss] = Xb[(size_t)(k0 + kk) * SPA + s0 + ss];
            }
        }
        __syncthreads();
        #pragma unroll
        for (int kk = 0; kk < 16; kk++) {
            float4 a  = *reinterpret_cast<const float4*>(&As[kk][ty * 4]);
            float4 bb = *reinterpret_cast<const float4*>(&Bs[kk][tx * 4]);
            float av[4] = {a.x, a.y, a.z, a.w};
            float bv[4] = {bb.x, bb.y, bb.z, bb.w};
            #pragma unroll
            for (int i = 0; i < 4; i++)
                #pragma unroll
                for (int j = 0; j < 4; j++)
                    acc[i][j] += av[i] * bv[j];
        }
        __syncthreads();
    }

    #pragma unroll
    for (int i = 0; i < 4; i++) {
        int o = o0 + ty * 4 + i;
        float bval = bias[o];
        size_t off = ((size_t)b * M + o) * SPA + s0 + tx * 4;
        float4 r;
        r.x = acc[i][0] + bval; r.y = acc[i][1] + bval;
        r.z = acc[i][2] + bval; r.w = acc[i][3] + bval;
        if (RESID) {
            float4 xr = *reinterpret_cast<const float4*>(&resid[off]);
            r.x += xr.x; r.y += xr.y; r.z += xr.z; r.w += xr.w;
        }
        *reinterpret_cast<float4*>(&Y[off]) = r;
    }
}

// ---------------------------------------------------------------------------
// Flash attention (fp32, SIMT). One block = one (b,h) x 64-query tile.
// Iterates 64-key tiles with online softmax. 16x16 threads, 4q x 4 per thread.
// ---------------------------------------------------------------------------
__global__ __launch_bounds__(256) void k_attn() {
    const int bh = blockIdx.y;
    const int b  = bh >> 2;       // NH = 4
    const int h  = bh & 3;
    const float* qb = g_qkv + ((size_t)b * 3 * CH + h * HD) * SPA;
    const float* kb = qb + (size_t)CH * SPA;
    const float* vb = qb + (size_t)2 * CH * SPA;
    const int q0 = blockIdx.x * 64;
    const int tid = threadIdx.x;
    const int tx = tid & 15, ty = tid >> 4;

    extern __shared__ float sm[];
    float* Qs = sm;               // [64][68]  Qs[d][i]
    float* Ks = Qs + 64 * 68;     // [64][68]  Ks[d][j]
    float* Vs = Ks + 64 * 68;     // [64][68]  Vs[j][d]  (transposed)
    float* Ps = Vs + 64 * 68;     // [64][68]  Ps[i][j]

    // load Q tile
    for (int idx = tid; idx < 64 * 64; idx += 256) {
        int d = idx >> 6, i = idx & 63;
        Qs[d * 68 + i] = qb[(size_t)d * SPA + q0 + i];
    }

    float m_run[4], l_run[4], o_acc[4][4];
    #pragma unroll
    for (int i = 0; i < 4; i++) {
        m_run[i] = -1e30f; l_run[i] = 0.f;
        #pragma unroll
        for (int u = 0; u < 4; u++) o_acc[i][u] = 0.f;
    }

    for (int t0 = 0; t0 < SPA; t0 += 64) {
        // load K [d][j] and V transposed [j][d]
        for (int idx = tid; idx < 64 * 64; idx += 256) {
            int d = idx >> 6, j = idx & 63;
            float kv = kb[(size_t)d * SPA + t0 + j];
            float vv = vb[(size_t)d * SPA + t0 + j];
            Ks[d * 68 + j] = kv;
            Vs[j * 68 + d] = vv;
        }
        __syncthreads();

        // scores: acc[i][j] = sum_d Qs[d][ty4+i] * Ks[d][tx4+j]
        float acc[4][4] = {};
        #pragma unroll 8
        for (int d = 0; d < 64; d++) {
            float4 qv = *reinterpret_cast<const float4*>(&Qs[d * 68 + ty * 4]);
            float4 kv = *reinterpret_cast<const float4*>(&Ks[d * 68 + tx * 4]);
            float qa[4] = {qv.x, qv.y, qv.z, qv.w};
            float ka[4] = {kv.x, kv.y, kv.z, kv.w};
            #pragma unroll
            for (int i = 0; i < 4; i++)
                #pragma unroll
                for (int j = 0; j < 4; j++)
                    acc[i][j] += qa[i] * ka[j];
        }

        // online softmax per query row (rows replicated across the 16 tx lanes)
        #pragma unroll
        for (int i = 0; i < 4; i++) {
            float s_[4];
            #pragma unroll
            for (int j = 0; j < 4; j++) s_[j] = acc[i][j] * SCALE;
            float mx = fmaxf(fmaxf(s_[0], s_[1]), fmaxf(s_[2], s_[3]));
            #pragma unroll
            for (int o = 1; o < 16; o <<= 1)
                mx = fmaxf(mx, __shfl_xor_sync(0xffffffffu, mx, o, 16));
            float mnew = fmaxf(m_run[i], mx);
            float p[4], rs = 0.f;
            #pragma unroll
            for (int j = 0; j < 4; j++) { p[j] = __expf(s_[j] - mnew); rs += p[j]; }
            #pragma unroll
            for (int o = 1; o < 16; o <<= 1)
                rs += __shfl_xor_sync(0xffffffffu, rs, o, 16);
            float alpha = __expf(m_run[i] - mnew);
            l_run[i] = l_run[i] * alpha + rs;
            m_run[i] = mnew;
            #pragma unroll
            for (int u = 0; u < 4; u++) o_acc[i][u] *= alpha;
            float4 pv = {p[0], p[1], p[2], p[3]};
            *reinterpret_cast<float4*>(&Ps[(ty * 4 + i) * 68 + tx * 4]) = pv;
        }
        __syncthreads();

        // PV: o_acc[i][u] += sum_j Ps[ty4+i][j] * Vs[j][tx4+u]
        #pragma unroll 4
        for (int j0 = 0; j0 < 64; j0 += 4) {
            float4 pr[4];
            #pragma unroll
            for (int i = 0; i < 4; i++)
                pr[i] = *reinterpret_cast<const float4*>(&Ps[(ty * 4 + i) * 68 + j0]);
            #pragma unroll
            for (int jj = 0; jj < 4; jj++) {
                float4 vv = *reinterpret_cast<const float4*>(&Vs[(j0 + jj) * 68 + tx * 4]);
                #pragma unroll
                for (int i = 0; i < 4; i++) {
                    float pij = (jj == 0) ? pr[i].x : (jj == 1) ? pr[i].y :
                                (jj == 2) ? pr[i].z : pr[i].w;
                    o_acc[i][0] += pij * vv.x;
                    o_acc[i][1] += pij * vv.y;
                    o_acc[i][2] += pij * vv.z;
                    o_acc[i][3] += pij * vv.w;
                }
            }
        }
        __syncthreads();
    }

    // stage normalized output through Ps for coalesced write: Ps[qi][dd]
    #pragma unroll
    for (int i = 0; i < 4; i++) {
        float inv = 1.0f / l_run[i];
        float4 r = {o_acc[i][0] * inv, o_acc[i][1] * inv,
                    o_acc[i][2] * inv, o_acc[i][3] * inv};
        *reinterpret_cast<float4*>(&Ps[(ty * 4 + i) * 68 + tx * 4]) = r;
    }
    __syncthreads();
    float* ob = g_ao + ((size_t)b * CH + h * HD) * SPA + q0;
    for (int idx = tid; idx < 64 * 64; idx += 256) {
        int dd = idx >> 6, j = idx & 63;
        ob[(size_t)dd * SPA + j] = Ps[j * 68 + dd];
    }
}

// ---------------------------------------------------------------------------
extern "C" void kernel_launch(void* const* d_in, const int* in_sizes, int n_in,
                              void* d_out, int out_size) {
    const float* x      = (const float*)d_in[0];
    const float* gamma  = (const float*)d_in[1];
    const float* beta   = (const float*)d_in[2];
    const float* w_qkv  = (const float*)d_in[3];
    const float* b_qkv  = (const float*)d_in[4];
    const float* w_proj = (const float*)d_in[5];
    const float* b_proj = (const float*)d_in[6];
    float* out = (float*)d_out;

    // pointers to device scratch
    float *xn_p, *qkv_p, *ao_p;
    cudaGetSymbolAddress((void**)&xn_p,  g_xn);
    cudaGetSymbolAddress((void**)&qkv_p, g_qkv);
    cudaGetSymbolAddress((void**)&ao_p,  g_ao);

    const size_t attn_smem = 4 * 64 * 68 * sizeof(float);  // ~68 KB
    cudaFuncSetAttribute(k_attn, cudaFuncAttributeMaxDynamicSharedMemorySize,
                         (int)attn_smem);

    // GroupNorm
    k_gn_part <<<BATCH * NGRP * PARTS, 256>>>(x);
    k_gn_final<<<1, 32>>>();
    k_gn_norm <<<(BATCH * CH * SPA) / 4 / 256, 256>>>(x, gamma, beta);

    // QKV GEMM: M=768
    {
        dim3 grid(SPA / 64, (3 * CH) / 64, BATCH);
        dim3 blk(16, 16);
        k_gemm<false><<<grid, blk>>>(w_qkv, b_qkv, xn_p, qkv_p, nullptr, 3 * CH);
    }

    // Flash attention
    {
        dim3 grid(SPA / 64, BATCH * NH);
        k_attn<<<grid, 256, attn_smem>>>();
    }

    // Proj GEMM + residual: M=256
    {
        dim3 grid(SPA / 64, CH / 64, BATCH);
        dim3 blk(16, 16);
        k_gemm<true><<<grid, blk>>>(w_proj, b_proj, ao_p, out, x, CH);
    }
}